// round 10
// baseline (speedup 1.0000x reference)
#include <cuda_runtime.h>
#include <math.h>

// SpectralConv2d: B=8, C=64, H=W=256, modes 16x16.
// Folded partial-DFT stages; k3 stages folded outputs through shared for
// coalesced STG.128 (store-issue path was the R6 bottleneck).

#define NIMG 512              // B*C images of 256x256

// tables (angle a = 2*pi/256)
__device__ float2 g_tab[256 * 16];   // [t][k] (cos akt, sin akt)
__device__ float  g_tabC[16 * 256];  // [k][t] cos
__device__ float  g_tabS[16 * 256];  // [k][t] sin
// k1 phase-1 folded table: [h][32] for h=0..63:
//   [0..7]  cos(a*(2m)*h)   [8..15] cos(a*(2m+1)*h)
//   [16..23] sin(a*(2m)*h)  [24..31] sin(a*(2m+1)*h)
__device__ float  g_tab1[64 * 32];
// X_ft corner per (b,i): [img][k*16+w], complex
__device__ float2 g_X[NIMG * 256];
// Z per (b,o): [img][p][j], j<16: cos-coeff, j>=16: sin-coeff
__device__ float  g_Z[(size_t)NIMG * 256 * 32];

// ---------------- table init ------------------------------------------------
__global__ void k_init() {
    int i = blockIdx.x * blockDim.x + threadIdx.x;
    if (i < 4096) {
        int t = i >> 4, k = i & 15;
        int m = (t * k) & 255;
        double s, c;
        sincospi((double)m / 128.0, &s, &c);       // angle = 2*pi*m/256
        g_tab[i] = make_float2((float)c, (float)s);
        g_tabC[k * 256 + t] = (float)c;
        g_tabS[k * 256 + t] = (float)s;
    }
    if (i < 2048) {
        int h = i >> 5, j = i & 31;
        int m = j & 7;
        int k = ((j & 15) < 8) ? (2 * m) : (2 * m + 1);
        int mm = (h * k) & 255;
        double s, c;
        sincospi((double)mm / 128.0, &s, &c);
        g_tab1[i] = (j < 16) ? (float)c : (float)s;
    }
}

// ---------------- K1: x -> A (folded partial DFT over H) -> corner W DFT ----
// Block = image, thread = x column. 40KB static smem (phase-2 basis via L1).
__global__ void __launch_bounds__(256) k1(const float* __restrict__ x) {
    __shared__ __align__(16) float  s_t1[64 * 32];   // 8KB
    __shared__ __align__(16) float2 s_A[16 * 256];   // 32KB
    int img = blockIdx.x, tid = threadIdx.x;

    for (int i = tid; i < 2048; i += 256) s_t1[i] = g_tab1[i];
    __syncthreads();

    // Phase 1: ar[k] = sum_h x[h]cos(akh), as[k] = sum_h x[h]sin(akh)
    const float* xp = x + (size_t)img * 65536 + tid;
    float x0   = xp[0];
    float x64v = xp[64 * 256];
    float x128 = xp[128 * 256];
    float x192 = xp[192 * 256];

    float arE[8], arO[8], asE[8], asO[8];
#pragma unroll
    for (int m = 0; m < 8; m++) { arE[m] = 0.f; arO[m] = 0.f; asE[m] = 0.f; asO[m] = 0.f; }

#pragma unroll 2
    for (int h = 1; h < 64; h++) {
        float a1 = xp[(size_t)h * 256];
        float a2 = xp[(size_t)(256 - h) * 256];
        float a3 = xp[(size_t)(128 - h) * 256];
        float a4 = xp[(size_t)(128 + h) * 256];
        float u1 = a1 + a2, v1 = a1 - a2;
        float u2 = a3 + a4, v2 = a3 - a4;
        float uE = u1 + u2, uO = u1 - u2;
        float vE = v1 - v2, vO = v1 + v2;
        const float4* t4 = (const float4*)(s_t1 + h * 32);   // broadcast LDS.128
        float4 cE0 = t4[0], cE1 = t4[1], cO0 = t4[2], cO1 = t4[3];
        float4 sE0 = t4[4], sE1 = t4[5], sO0 = t4[6], sO1 = t4[7];
        arE[0] = fmaf(uE, cE0.x, arE[0]); arE[1] = fmaf(uE, cE0.y, arE[1]);
        arE[2] = fmaf(uE, cE0.z, arE[2]); arE[3] = fmaf(uE, cE0.w, arE[3]);
        arE[4] = fmaf(uE, cE1.x, arE[4]); arE[5] = fmaf(uE, cE1.y, arE[5]);
        arE[6] = fmaf(uE, cE1.z, arE[6]); arE[7] = fmaf(uE, cE1.w, arE[7]);
        arO[0] = fmaf(uO, cO0.x, arO[0]); arO[1] = fmaf(uO, cO0.y, arO[1]);
        arO[2] = fmaf(uO, cO0.z, arO[2]); arO[3] = fmaf(uO, cO0.w, arO[3]);
        arO[4] = fmaf(uO, cO1.x, arO[4]); arO[5] = fmaf(uO, cO1.y, arO[5]);
        arO[6] = fmaf(uO, cO1.z, arO[6]); arO[7] = fmaf(uO, cO1.w, arO[7]);
        asE[0] = fmaf(vE, sE0.x, asE[0]); asE[1] = fmaf(vE, sE0.y, asE[1]);
        asE[2] = fmaf(vE, sE0.z, asE[2]); asE[3] = fmaf(vE, sE0.w, asE[3]);
        asE[4] = fmaf(vE, sE1.x, asE[4]); asE[5] = fmaf(vE, sE1.y, asE[5]);
        asE[6] = fmaf(vE, sE1.z, asE[6]); asE[7] = fmaf(vE, sE1.w, asE[7]);
        asO[0] = fmaf(vO, sO0.x, asO[0]); asO[1] = fmaf(vO, sO0.y, asO[1]);
        asO[2] = fmaf(vO, sO0.z, asO[2]); asO[3] = fmaf(vO, sO0.w, asO[3]);
        asO[4] = fmaf(vO, sO1.x, asO[4]); asO[5] = fmaf(vO, sO1.y, asO[5]);
        asO[6] = fmaf(vO, sO1.z, asO[6]); asO[7] = fmaf(vO, sO1.w, asO[7]);
    }

    // boundary terms: h=0,64,128,192
    float u64v = x64v + x192, v64v = x64v - x192;
    float sgn = 1.f;
#pragma unroll
    for (int m = 0; m < 8; m++) {
        s_A[(2 * m) * 256 + tid]     = make_float2(x0 + x128 + arE[m] + sgn * u64v, asE[m]);
        s_A[(2 * m + 1) * 256 + tid] = make_float2(x0 - x128 + arO[m], asO[m] + sgn * v64v);
        sgn = -sgn;
    }
    __syncthreads();

    // Phase 2: X[k,w] = sum_x (ar - i*as)(cos - i sin); basis from L1 (g_tab)
    int k = tid >> 4, w = tid & 15;
    float xr = 0.f, xi = 0.f;
#pragma unroll 4
    for (int xx = 0; xx < 256; xx++) {
        float2 a  = s_A[k * 256 + xx];            // broadcast LDS
        float2 cs = __ldg(&g_tab[xx * 16 + w]);   // 128B/warp, L1-resident
        xr += a.x * cs.x - a.y * cs.y;
        xi -= a.y * cs.x + a.x * cs.y;
    }
    g_X[img * 256 + tid] = make_float2(xr, xi);
}

// ---------------- K2 (fused): channel mix + inverse-k DFT -> Z --------------
__global__ void __launch_bounds__(256) k2(const float* __restrict__ wre,
                                          const float* __restrict__ wim) {
    __shared__ float2 sG[256];
    int b = blockIdx.x >> 6, o = blockIdx.x & 63, tid = threadIdx.x;

    // Phase A: G[k,w] = sum_i X[b,i,k,w] * (wr + i wi);  tid = k*16+w
    {
        const float2* Xb = g_X + b * 64 * 256;
        float gr = 0.f, gi = 0.f;
#pragma unroll 4
        for (int i = 0; i < 64; i++) {
            float2 xv = Xb[i * 256 + tid];
            float wr = wre[(size_t)(i * 64 + o) * 256 + tid];
            float wi = wim[(size_t)(i * 64 + o) * 256 + tid];
            gr = fmaf(xv.x, wr, fmaf(-xv.y, wi, gr));
            gi = fmaf(xv.x, wi, fmaf( xv.y, wr, gi));
        }
        sG[tid] = make_float2(gr, gi);
    }
    __syncthreads();

    // Phase B: Y[p,w] = sum_k G[k,w] e^{+i a k p};  tid = p
    int p = tid;
    float2 tp[16];
#pragma unroll
    for (int k = 0; k < 16; k++)
        tp[k] = make_float2(g_tabC[k * 256 + p], g_tabS[k * 256 + p]);  // coalesced

    float zc[16], zs[16];
#pragma unroll
    for (int w = 0; w < 16; w++) {
        float yr = 0.f, yi = 0.f;
#pragma unroll
        for (int k = 0; k < 16; k++) {
            float2 g = sG[k * 16 + w];
            yr += g.x * tp[k].x - g.y * tp[k].y;
            yi += g.x * tp[k].y + g.y * tp[k].x;
        }
        zc[w] = yr; zs[w] = -yi;
    }
    const float s1 = 1.0f / 65536.0f, s2 = 2.0f / 65536.0f;
    zc[0] *= s1; zs[0] = 0.f;
#pragma unroll
    for (int w = 1; w < 16; w++) { zc[w] *= s2; zs[w] *= s2; }

    float4* z4 = (float4*)(g_Z + ((size_t)blockIdx.x * 256 + p) * 32);
    z4[0] = make_float4(zc[0],  zc[1],  zc[2],  zc[3]);
    z4[1] = make_float4(zc[4],  zc[5],  zc[6],  zc[7]);
    z4[2] = make_float4(zc[8],  zc[9],  zc[10], zc[11]);
    z4[3] = make_float4(zc[12], zc[13], zc[14], zc[15]);
    z4[4] = make_float4(zs[0],  zs[1],  zs[2],  zs[3]);
    z4[5] = make_float4(zs[4],  zs[5],  zs[6],  zs[7]);
    z4[6] = make_float4(zs[8],  zs[9],  zs[10], zs[11]);
    z4[7] = make_float4(zs[12], zs[13], zs[14], zs[15]);
}

// ---------------- K3: folded inverse W transform, staged coalesced stores ---
// Grid = NIMG*4; block owns 64 p-rows. Folded math (4 outputs per thread-row),
// outputs staged in shared -> STG.128 coalesced writes.
__global__ void __launch_bounds__(256) k3(float* __restrict__ out) {
    __shared__ __align__(16) float s_z[64 * 32];     // 8KB  z tile
    __shared__ __align__(16) float s_out[16 * 256];  // 16KB staging (16 rows)
    int img = blockIdx.x >> 2, tile = blockIdx.x & 3, tid = threadIdx.x;

    {   // load z tile: rows [tile*64, tile*64+64), contiguous 8KB
        const float4* zsrc = (const float4*)(g_Z + (size_t)img * 8192 + tile * 2048);
        float4* zdst = (float4*)s_z;
        zdst[tid] = zsrc[tid];
        zdst[tid + 256] = zsrc[tid + 256];
    }
    __syncthreads();

    int qs = tid & 63, pg = tid >> 6;
    float c[16], s[16];
    if (qs != 0) {
#pragma unroll
        for (int w = 0; w < 16; w++) {
            float2 cs = g_tab[qs * 16 + w];
            c[w] = cs.x; s[w] = cs.y;
        }
    }

    float* ob = out + (size_t)img * 65536 + (size_t)tile * 64 * 256;

    for (int chunk = 0; chunk < 4; chunk++) {
#pragma unroll
        for (int rr = 0; rr < 4; rr++) {
            int ric = pg * 4 + rr;                   // row-in-chunk 0..15
            const float* z = s_z + (chunk * 16 + ric) * 32;
            float* so = s_out + ric * 256;
            if (qs == 0) {
                float o0 = 0.f, o128 = 0.f, c64 = 0.f, s64 = 0.f;
#pragma unroll
                for (int w = 0; w < 16; w++) {
                    float v = z[w];
                    o0 += v;
                    o128 += (w & 1) ? -v : v;
                }
#pragma unroll
                for (int m = 0; m < 4; m++) {
                    c64 += z[4 * m]          - z[4 * m + 2];
                    s64 += z[16 + 4 * m + 1] - z[16 + 4 * m + 3];
                }
                so[0]   = o0;
                so[128] = o128;
                so[64]  = c64 + s64;
                so[192] = c64 - s64;
            } else {
                const float4* z4 = (const float4*)z;  // broadcast LDS.128
                float zz[32];
#pragma unroll
                for (int t = 0; t < 8; t++) {
                    float4 v = z4[t];
                    zz[4 * t] = v.x; zz[4 * t + 1] = v.y;
                    zz[4 * t + 2] = v.z; zz[4 * t + 3] = v.w;
                }
                float Ce = 0.f, Co = 0.f, Se = 0.f, So = 0.f;
#pragma unroll
                for (int m = 0; m < 8; m++) {
                    Ce = fmaf(zz[2 * m],          c[2 * m],     Ce);
                    Co = fmaf(zz[2 * m + 1],      c[2 * m + 1], Co);
                    Se = fmaf(zz[16 + 2 * m],     s[2 * m],     Se);
                    So = fmaf(zz[16 + 2 * m + 1], s[2 * m + 1], So);
                }
                float t1 = Ce + Co, t2 = Se + So;
                float t3 = Ce - Co, t4 = So - Se;
                so[qs]       = t1 + t2;
                so[256 - qs] = t1 - t2;
                so[128 - qs] = t3 + t4;
                so[128 + qs] = t3 - t4;
            }
        }
        __syncthreads();
        // coalesced copy: 16 rows x 256 floats = 1024 float4
        {
            const float4* src = (const float4*)s_out;
            float4* dst = (float4*)(ob + (size_t)chunk * 16 * 256);
            dst[tid]       = src[tid];
            dst[tid + 256] = src[tid + 256];
            dst[tid + 512] = src[tid + 512];
            dst[tid + 768] = src[tid + 768];
        }
        __syncthreads();
    }
}

extern "C" void kernel_launch(void* const* d_in, const int* in_sizes, int n_in,
                              void* d_out, int out_size) {
    const float* x   = (const float*)d_in[0];
    const float* wre = (const float*)d_in[1];
    const float* wim = (const float*)d_in[2];
    float* out = (float*)d_out;

    k_init<<<16, 256>>>();
    k1 <<<NIMG, 256>>>(x);
    k2 <<<NIMG, 256>>>(wre, wim);
    k3 <<<NIMG * 4, 256>>>(out);
}

// round 11
// speedup vs baseline: 1.0688x; 1.0688x over previous
#include <cuda_runtime.h>
#include <math.h>

// SpectralConv2d: B=8, C=64, H=W=256, modes 16x16.
// Folded partial-DFT stages (4x FMA reduction on the big stages).
// R10: k1/k2 = known-good 162.5us versions; k3 = folded direct stores with
// fine-grained tiling (8KB smem/block) for occupancy.

#define NIMG 512              // B*C images of 256x256

// tables (angle a = 2*pi/256)
__device__ float2 g_tab[256 * 16];   // [t][k] (cos akt, sin akt)
__device__ float  g_tabC[16 * 256];  // [k][t] cos
__device__ float  g_tabS[16 * 256];  // [k][t] sin
// k1 phase-1 folded table: [h][32] for h=0..63:
//   [0..7]  cos(a*(2m)*h)   [8..15] cos(a*(2m+1)*h)
//   [16..23] sin(a*(2m)*h)  [24..31] sin(a*(2m+1)*h)
__device__ float  g_tab1[64 * 32];
// X_ft corner per (b,i): [img][k*16+w], complex
__device__ float2 g_X[NIMG * 256];
// Z per (b,o): [img][p][j], j<16: cos-coeff, j>=16: sin-coeff
__device__ float  g_Z[(size_t)NIMG * 256 * 32];

// ---------------- table init ------------------------------------------------
__global__ void k_init() {
    int i = blockIdx.x * blockDim.x + threadIdx.x;
    if (i < 4096) {
        int t = i >> 4, k = i & 15;
        int m = (t * k) & 255;
        double s, c;
        sincospi((double)m / 128.0, &s, &c);       // angle = 2*pi*m/256
        g_tab[i] = make_float2((float)c, (float)s);
        g_tabC[k * 256 + t] = (float)c;
        g_tabS[k * 256 + t] = (float)s;
    }
    if (i < 2048) {
        int h = i >> 5, j = i & 31;
        int m = j & 7;
        int k = ((j & 15) < 8) ? (2 * m) : (2 * m + 1);
        int mm = (h * k) & 255;
        double s, c;
        sincospi((double)mm / 128.0, &s, &c);
        g_tab1[i] = (j < 16) ? (float)c : (float)s;
    }
}

// ---------------- K1: x -> A (folded partial DFT over H) -> corner W DFT ----
// Block = image, thread = x column. (162.5us-run version, unchanged.)
__global__ void __launch_bounds__(256) k1(const float* __restrict__ x) {
    extern __shared__ __align__(16) char smem_raw[];
    float*  s_t1  = (float*)smem_raw;                   // [64][32]  8KB
    float2* s_tab = (float2*)(smem_raw + 8192);         // [t][16]  32KB
    float2* s_A   = (float2*)(smem_raw + 8192 + 32768); // [k][x]   32KB
    int img = blockIdx.x, tid = threadIdx.x;

    for (int i = tid; i < 2048; i += 256) s_t1[i] = g_tab1[i];
    for (int i = tid; i < 4096; i += 256) s_tab[i] = g_tab[i];
    __syncthreads();

    // Phase 1: ar[k] = sum_h x[h]cos(akh), as[k] = sum_h x[h]sin(akh)
    const float* xp = x + (size_t)img * 65536 + tid;
    float x0   = xp[0];
    float x64v = xp[64 * 256];
    float x128 = xp[128 * 256];
    float x192 = xp[192 * 256];

    float arE[8], arO[8], asE[8], asO[8];
#pragma unroll
    for (int m = 0; m < 8; m++) { arE[m] = 0.f; arO[m] = 0.f; asE[m] = 0.f; asO[m] = 0.f; }

#pragma unroll 2
    for (int h = 1; h < 64; h++) {
        float a1 = xp[(size_t)h * 256];
        float a2 = xp[(size_t)(256 - h) * 256];
        float a3 = xp[(size_t)(128 - h) * 256];
        float a4 = xp[(size_t)(128 + h) * 256];
        float u1 = a1 + a2, v1 = a1 - a2;
        float u2 = a3 + a4, v2 = a3 - a4;
        float uE = u1 + u2, uO = u1 - u2;
        float vE = v1 - v2, vO = v1 + v2;
        const float4* t4 = (const float4*)(s_t1 + h * 32);   // broadcast LDS.128
        float4 cE0 = t4[0], cE1 = t4[1], cO0 = t4[2], cO1 = t4[3];
        float4 sE0 = t4[4], sE1 = t4[5], sO0 = t4[6], sO1 = t4[7];
        arE[0] = fmaf(uE, cE0.x, arE[0]); arE[1] = fmaf(uE, cE0.y, arE[1]);
        arE[2] = fmaf(uE, cE0.z, arE[2]); arE[3] = fmaf(uE, cE0.w, arE[3]);
        arE[4] = fmaf(uE, cE1.x, arE[4]); arE[5] = fmaf(uE, cE1.y, arE[5]);
        arE[6] = fmaf(uE, cE1.z, arE[6]); arE[7] = fmaf(uE, cE1.w, arE[7]);
        arO[0] = fmaf(uO, cO0.x, arO[0]); arO[1] = fmaf(uO, cO0.y, arO[1]);
        arO[2] = fmaf(uO, cO0.z, arO[2]); arO[3] = fmaf(uO, cO0.w, arO[3]);
        arO[4] = fmaf(uO, cO1.x, arO[4]); arO[5] = fmaf(uO, cO1.y, arO[5]);
        arO[6] = fmaf(uO, cO1.z, arO[6]); arO[7] = fmaf(uO, cO1.w, arO[7]);
        asE[0] = fmaf(vE, sE0.x, asE[0]); asE[1] = fmaf(vE, sE0.y, asE[1]);
        asE[2] = fmaf(vE, sE0.z, asE[2]); asE[3] = fmaf(vE, sE0.w, asE[3]);
        asE[4] = fmaf(vE, sE1.x, asE[4]); asE[5] = fmaf(vE, sE1.y, asE[5]);
        asE[6] = fmaf(vE, sE1.z, asE[6]); asE[7] = fmaf(vE, sE1.w, asE[7]);
        asO[0] = fmaf(vO, sO0.x, asO[0]); asO[1] = fmaf(vO, sO0.y, asO[1]);
        asO[2] = fmaf(vO, sO0.z, asO[2]); asO[3] = fmaf(vO, sO0.w, asO[3]);
        asO[4] = fmaf(vO, sO1.x, asO[4]); asO[5] = fmaf(vO, sO1.y, asO[5]);
        asO[6] = fmaf(vO, sO1.z, asO[6]); asO[7] = fmaf(vO, sO1.w, asO[7]);
    }

    // boundary terms: h=0,64,128,192
    float u64v = x64v + x192, v64v = x64v - x192;
    float sgn = 1.f;
#pragma unroll
    for (int m = 0; m < 8; m++) {
        s_A[(2 * m) * 256 + tid]     = make_float2(x0 + x128 + arE[m] + sgn * u64v, asE[m]);
        s_A[(2 * m + 1) * 256 + tid] = make_float2(x0 - x128 + arO[m], asO[m] + sgn * v64v);
        sgn = -sgn;
    }
    __syncthreads();

    // Phase 2: X[k,w] = sum_x (ar - i*as)(cos - i sin)
    int k = tid >> 4, w = tid & 15;
    float xr = 0.f, xi = 0.f;
#pragma unroll 4
    for (int xx = 0; xx < 256; xx++) {
        float2 a  = s_A[k * 256 + xx];     // broadcast
        float2 cs = s_tab[xx * 16 + w];
        xr += a.x * cs.x - a.y * cs.y;
        xi -= a.y * cs.x + a.x * cs.y;
    }
    g_X[img * 256 + tid] = make_float2(xr, xi);
}

// ---------------- K2 (fused): channel mix + inverse-k DFT -> Z --------------
__global__ void __launch_bounds__(256) k2(const float* __restrict__ wre,
                                          const float* __restrict__ wim) {
    __shared__ float2 sG[256];
    int b = blockIdx.x >> 6, o = blockIdx.x & 63, tid = threadIdx.x;

    // Phase A: G[k,w] = sum_i X[b,i,k,w] * (wr + i wi);  tid = k*16+w
    {
        const float2* Xb = g_X + b * 64 * 256;
        float gr = 0.f, gi = 0.f;
#pragma unroll 4
        for (int i = 0; i < 64; i++) {
            float2 xv = Xb[i * 256 + tid];
            float wr = wre[(size_t)(i * 64 + o) * 256 + tid];
            float wi = wim[(size_t)(i * 64 + o) * 256 + tid];
            gr = fmaf(xv.x, wr, fmaf(-xv.y, wi, gr));
            gi = fmaf(xv.x, wi, fmaf( xv.y, wr, gi));
        }
        sG[tid] = make_float2(gr, gi);
    }
    __syncthreads();

    // Phase B: Y[p,w] = sum_k G[k,w] e^{+i a k p};  tid = p
    int p = tid;
    float2 tp[16];
#pragma unroll
    for (int k = 0; k < 16; k++)
        tp[k] = make_float2(g_tabC[k * 256 + p], g_tabS[k * 256 + p]);  // coalesced

    float zc[16], zs[16];
#pragma unroll
    for (int w = 0; w < 16; w++) {
        float yr = 0.f, yi = 0.f;
#pragma unroll
        for (int k = 0; k < 16; k++) {
            float2 g = sG[k * 16 + w];
            yr += g.x * tp[k].x - g.y * tp[k].y;
            yi += g.x * tp[k].y + g.y * tp[k].x;
        }
        zc[w] = yr; zs[w] = -yi;
    }
    const float s1 = 1.0f / 65536.0f, s2 = 2.0f / 65536.0f;
    zc[0] *= s1; zs[0] = 0.f;
#pragma unroll
    for (int w = 1; w < 16; w++) { zc[w] *= s2; zs[w] *= s2; }

    float4* z4 = (float4*)(g_Z + ((size_t)blockIdx.x * 256 + p) * 32);
    z4[0] = make_float4(zc[0],  zc[1],  zc[2],  zc[3]);
    z4[1] = make_float4(zc[4],  zc[5],  zc[6],  zc[7]);
    z4[2] = make_float4(zc[8],  zc[9],  zc[10], zc[11]);
    z4[3] = make_float4(zc[12], zc[13], zc[14], zc[15]);
    z4[4] = make_float4(zs[0],  zs[1],  zs[2],  zs[3]);
    z4[5] = make_float4(zs[4],  zs[5],  zs[6],  zs[7]);
    z4[6] = make_float4(zs[8],  zs[9],  zs[10], zs[11]);
    z4[7] = make_float4(zs[12], zs[13], zs[14], zs[15]);
}

// ---------------- K3: folded inverse W transform, tiled for occupancy -------
// Grid = NIMG*4; block owns 64 p-rows (8KB z-tile). qs in 1..63 -> 4 outputs
// per row (q, 256-q, 128-q, 128+q); qs==0 handles q in {0,64,128,192}.
// Direct STG: each folded stream is a dense 128B warp segment.
__global__ void __launch_bounds__(256) k3(float* __restrict__ out) {
    __shared__ __align__(16) float s_z[64 * 32];    // 8KB z tile
    int img = blockIdx.x >> 2, tile = blockIdx.x & 3, tid = threadIdx.x;
    {
        const float4* zsrc = (const float4*)(g_Z + (size_t)img * 8192 + tile * 2048);
        float4* zdst = (float4*)s_z;
        zdst[tid]       = zsrc[tid];
        zdst[tid + 256] = zsrc[tid + 256];
    }
    __syncthreads();

    int qs = tid & 63, pg = tid >> 6;               // 4 p-groups of 16 rows
    float* ob = out + (size_t)img * 65536 + (size_t)tile * 64 * 256;

    if (qs == 0) {
        for (int pi = 0; pi < 16; pi++) {
            int p = pg * 16 + pi;
            const float* z = s_z + p * 32;
            float o0 = 0.f, o128 = 0.f, c64 = 0.f, s64 = 0.f;
#pragma unroll
            for (int w = 0; w < 16; w++) {
                float v = z[w];
                o0 += v;
                o128 += (w & 1) ? -v : v;
            }
#pragma unroll
            for (int m = 0; m < 4; m++) {
                c64 += z[4 * m]          - z[4 * m + 2];
                s64 += z[16 + 4 * m + 1] - z[16 + 4 * m + 3];
            }
            float* op = ob + (size_t)p * 256;
            op[0]   = o0;
            op[128] = o128;
            op[64]  = c64 + s64;
            op[192] = c64 - s64;
        }
    } else {
        float c[16], s[16];
#pragma unroll
        for (int w = 0; w < 16; w++) {
            float2 cs = g_tab[qs * 16 + w];
            c[w] = cs.x; s[w] = cs.y;
        }
        for (int pi = 0; pi < 16; pi++) {
            int p = pg * 16 + pi;
            const float4* z4 = (const float4*)(s_z + p * 32);  // broadcast LDS.128
            float z[32];
#pragma unroll
            for (int t = 0; t < 8; t++) {
                float4 v = z4[t];
                z[4 * t] = v.x; z[4 * t + 1] = v.y; z[4 * t + 2] = v.z; z[4 * t + 3] = v.w;
            }
            float Ce = 0.f, Co = 0.f, Se = 0.f, So = 0.f;
#pragma unroll
            for (int m = 0; m < 8; m++) {
                Ce = fmaf(z[2 * m],          c[2 * m],     Ce);
                Co = fmaf(z[2 * m + 1],      c[2 * m + 1], Co);
                Se = fmaf(z[16 + 2 * m],     s[2 * m],     Se);
                So = fmaf(z[16 + 2 * m + 1], s[2 * m + 1], So);
            }
            float t1 = Ce + Co, t2 = Se + So;
            float t3 = Ce - Co, t4 = So - Se;
            float* op = ob + (size_t)p * 256;
            op[qs]        = t1 + t2;
            op[256 - qs]  = t1 - t2;
            op[128 - qs]  = t3 + t4;
            op[128 + qs]  = t3 - t4;
        }
    }
}

extern "C" void kernel_launch(void* const* d_in, const int* in_sizes, int n_in,
                              void* d_out, int out_size) {
    const float* x   = (const float*)d_in[0];
    const float* wre = (const float*)d_in[1];
    const float* wim = (const float*)d_in[2];
    float* out = (float*)d_out;

    cudaFuncSetAttribute(k1, cudaFuncAttributeMaxDynamicSharedMemorySize, 73728);

    k_init<<<16, 256>>>();
    k1 <<<NIMG, 256, 73728>>>(x);
    k2 <<<NIMG, 256>>>(wre, wim);
    k3 <<<NIMG * 4, 256>>>(out);
}

// round 13
// speedup vs baseline: 1.3568x; 1.2695x over previous
#include <cuda_runtime.h>
#include <math.h>

// SpectralConv2d: B=8, C=64, H=W=256, modes 16x16.
// Folded partial-DFT stages (4x FMA reduction on the big stages).
// R11: k3 = tiled + smem-staged transposed basis + divergence-free specials.

#define NIMG 512              // B*C images of 256x256

// tables (angle a = 2*pi/256)
__device__ float2 g_tab[256 * 16];   // [t][k] (cos akt, sin akt)
__device__ float  g_tabC[16 * 256];  // [k][t] cos
__device__ float  g_tabS[16 * 256];  // [k][t] sin
// k1 phase-1 folded table: [h][32] for h=0..63
__device__ float  g_tab1[64 * 32];
// X_ft corner per (b,i): [img][k*16+w], complex
__device__ float2 g_X[NIMG * 256];
// Z per (b,o): [img][p][j], j<16: cos-coeff, j>=16: sin-coeff
__device__ float  g_Z[(size_t)NIMG * 256 * 32];

// ---------------- table init ------------------------------------------------
__global__ void k_init() {
    int i = blockIdx.x * blockDim.x + threadIdx.x;
    if (i < 4096) {
        int t = i >> 4, k = i & 15;
        int m = (t * k) & 255;
        double s, c;
        sincospi((double)m / 128.0, &s, &c);       // angle = 2*pi*m/256
        g_tab[i] = make_float2((float)c, (float)s);
        g_tabC[k * 256 + t] = (float)c;
        g_tabS[k * 256 + t] = (float)s;
    }
    if (i < 2048) {
        int h = i >> 5, j = i & 31;
        int m = j & 7;
        int k = ((j & 15) < 8) ? (2 * m) : (2 * m + 1);
        int mm = (h * k) & 255;
        double s, c;
        sincospi((double)mm / 128.0, &s, &c);
        g_tab1[i] = (j < 16) ? (float)c : (float)s;
    }
}

// ---------------- K1: x -> A (folded partial DFT over H) -> corner W DFT ----
// Block = image, thread = x column. (162.5us-run version, unchanged.)
__global__ void __launch_bounds__(256) k1(const float* __restrict__ x) {
    extern __shared__ __align__(16) char smem_raw[];
    float*  s_t1  = (float*)smem_raw;                   // [64][32]  8KB
    float2* s_tab = (float2*)(smem_raw + 8192);         // [t][16]  32KB
    float2* s_A   = (float2*)(smem_raw + 8192 + 32768); // [k][x]   32KB
    int img = blockIdx.x, tid = threadIdx.x;

    for (int i = tid; i < 2048; i += 256) s_t1[i] = g_tab1[i];
    for (int i = tid; i < 4096; i += 256) s_tab[i] = g_tab[i];
    __syncthreads();

    const float* xp = x + (size_t)img * 65536 + tid;
    float x0   = xp[0];
    float x64v = xp[64 * 256];
    float x128 = xp[128 * 256];
    float x192 = xp[192 * 256];

    float arE[8], arO[8], asE[8], asO[8];
#pragma unroll
    for (int m = 0; m < 8; m++) { arE[m] = 0.f; arO[m] = 0.f; asE[m] = 0.f; asO[m] = 0.f; }

#pragma unroll 2
    for (int h = 1; h < 64; h++) {
        float a1 = xp[(size_t)h * 256];
        float a2 = xp[(size_t)(256 - h) * 256];
        float a3 = xp[(size_t)(128 - h) * 256];
        float a4 = xp[(size_t)(128 + h) * 256];
        float u1 = a1 + a2, v1 = a1 - a2;
        float u2 = a3 + a4, v2 = a3 - a4;
        float uE = u1 + u2, uO = u1 - u2;
        float vE = v1 - v2, vO = v1 + v2;
        const float4* t4 = (const float4*)(s_t1 + h * 32);   // broadcast LDS.128
        float4 cE0 = t4[0], cE1 = t4[1], cO0 = t4[2], cO1 = t4[3];
        float4 sE0 = t4[4], sE1 = t4[5], sO0 = t4[6], sO1 = t4[7];
        arE[0] = fmaf(uE, cE0.x, arE[0]); arE[1] = fmaf(uE, cE0.y, arE[1]);
        arE[2] = fmaf(uE, cE0.z, arE[2]); arE[3] = fmaf(uE, cE0.w, arE[3]);
        arE[4] = fmaf(uE, cE1.x, arE[4]); arE[5] = fmaf(uE, cE1.y, arE[5]);
        arE[6] = fmaf(uE, cE1.z, arE[6]); arE[7] = fmaf(uE, cE1.w, arE[7]);
        arO[0] = fmaf(uO, cO0.x, arO[0]); arO[1] = fmaf(uO, cO0.y, arO[1]);
        arO[2] = fmaf(uO, cO0.z, arO[2]); arO[3] = fmaf(uO, cO0.w, arO[3]);
        arO[4] = fmaf(uO, cO1.x, arO[4]); arO[5] = fmaf(uO, cO1.y, arO[5]);
        arO[6] = fmaf(uO, cO1.z, arO[6]); arO[7] = fmaf(uO, cO1.w, arO[7]);
        asE[0] = fmaf(vE, sE0.x, asE[0]); asE[1] = fmaf(vE, sE0.y, asE[1]);
        asE[2] = fmaf(vE, sE0.z, asE[2]); asE[3] = fmaf(vE, sE0.w, asE[3]);
        asE[4] = fmaf(vE, sE1.x, asE[4]); asE[5] = fmaf(vE, sE1.y, asE[5]);
        asE[6] = fmaf(vE, sE1.z, asE[6]); asE[7] = fmaf(vE, sE1.w, asE[7]);
        asO[0] = fmaf(vO, sO0.x, asO[0]); asO[1] = fmaf(vO, sO0.y, asO[1]);
        asO[2] = fmaf(vO, sO0.z, asO[2]); asO[3] = fmaf(vO, sO0.w, asO[3]);
        asO[4] = fmaf(vO, sO1.x, asO[4]); asO[5] = fmaf(vO, sO1.y, asO[5]);
        asO[6] = fmaf(vO, sO1.z, asO[6]); asO[7] = fmaf(vO, sO1.w, asO[7]);
    }

    float u64v = x64v + x192, v64v = x64v - x192;
    float sgn = 1.f;
#pragma unroll
    for (int m = 0; m < 8; m++) {
        s_A[(2 * m) * 256 + tid]     = make_float2(x0 + x128 + arE[m] + sgn * u64v, asE[m]);
        s_A[(2 * m + 1) * 256 + tid] = make_float2(x0 - x128 + arO[m], asO[m] + sgn * v64v);
        sgn = -sgn;
    }
    __syncthreads();

    int k = tid >> 4, w = tid & 15;
    float xr = 0.f, xi = 0.f;
#pragma unroll 4
    for (int xx = 0; xx < 256; xx++) {
        float2 a  = s_A[k * 256 + xx];     // broadcast
        float2 cs = s_tab[xx * 16 + w];
        xr += a.x * cs.x - a.y * cs.y;
        xi -= a.y * cs.x + a.x * cs.y;
    }
    g_X[img * 256 + tid] = make_float2(xr, xi);
}

// ---------------- K2 (fused): channel mix + inverse-k DFT -> Z --------------
__global__ void __launch_bounds__(256) k2(const float* __restrict__ wre,
                                          const float* __restrict__ wim) {
    __shared__ float2 sG[256];
    int b = blockIdx.x >> 6, o = blockIdx.x & 63, tid = threadIdx.x;

    {
        const float2* Xb = g_X + b * 64 * 256;
        float gr = 0.f, gi = 0.f;
#pragma unroll 4
        for (int i = 0; i < 64; i++) {
            float2 xv = Xb[i * 256 + tid];
            float wr = wre[(size_t)(i * 64 + o) * 256 + tid];
            float wi = wim[(size_t)(i * 64 + o) * 256 + tid];
            gr = fmaf(xv.x, wr, fmaf(-xv.y, wi, gr));
            gi = fmaf(xv.x, wi, fmaf( xv.y, wr, gi));
        }
        sG[tid] = make_float2(gr, gi);
    }
    __syncthreads();

    int p = tid;
    float2 tp[16];
#pragma unroll
    for (int k = 0; k < 16; k++)
        tp[k] = make_float2(g_tabC[k * 256 + p], g_tabS[k * 256 + p]);

    float zc[16], zs[16];
#pragma unroll
    for (int w = 0; w < 16; w++) {
        float yr = 0.f, yi = 0.f;
#pragma unroll
        for (int k = 0; k < 16; k++) {
            float2 g = sG[k * 16 + w];
            yr += g.x * tp[k].x - g.y * tp[k].y;
            yi += g.x * tp[k].y + g.y * tp[k].x;
        }
        zc[w] = yr; zs[w] = -yi;
    }
    const float s1 = 1.0f / 65536.0f, s2 = 2.0f / 65536.0f;
    zc[0] *= s1; zs[0] = 0.f;
#pragma unroll
    for (int w = 1; w < 16; w++) { zc[w] *= s2; zs[w] *= s2; }

    float4* z4 = (float4*)(g_Z + ((size_t)blockIdx.x * 256 + p) * 32);
    z4[0] = make_float4(zc[0],  zc[1],  zc[2],  zc[3]);
    z4[1] = make_float4(zc[4],  zc[5],  zc[6],  zc[7]);
    z4[2] = make_float4(zc[8],  zc[9],  zc[10], zc[11]);
    z4[3] = make_float4(zc[12], zc[13], zc[14], zc[15]);
    z4[4] = make_float4(zs[0],  zs[1],  zs[2],  zs[3]);
    z4[5] = make_float4(zs[4],  zs[5],  zs[6],  zs[7]);
    z4[6] = make_float4(zs[8],  zs[9],  zs[10], zs[11]);
    z4[7] = make_float4(zs[12], zs[13], zs[14], zs[15]);
}

// ---------------- K3: folded inverse W transform ----------------------------
// Grid = NIMG*4; block owns 64 p-rows. Basis staged in smem transposed
// ([w][qs], stride 65 -> conflict-free). Main loop: qs=1..63 generic fold,
// 4 outputs/row. Specials q in {0,64,128,192} in a uniform tail (warps 0-1).
// s_z padded to stride 36 (16B-aligned, de-conflicts tail scalar reads).
#define ZS 36
__global__ void __launch_bounds__(256) k3(float* __restrict__ out) {
    __shared__ __align__(16) float s_z[64 * ZS];     // 9KB z tile (padded)
    __shared__ float s_bc[16 * 65];                  // basis cos [w][qs]
    __shared__ float s_bs[16 * 65];                  // basis sin [w][qs]
    int img = blockIdx.x >> 2, tile = blockIdx.x & 3, tid = threadIdx.x;

    {   // stage z tile (2048 floats) into padded layout
        const float4* zsrc = (const float4*)(g_Z + (size_t)img * 8192 + tile * 2048);
        float4* zdst = (float4*)s_z;
#pragma unroll
        for (int it = 0; it < 2; it++) {
            int i = tid + it * 256;                  // 0..511 float4s
            int row = i >> 3, t = i & 7;
            zdst[row * (ZS / 4) + t] = zsrc[i];
        }
    }
    // stage basis transposed: g_tab[t][k] -> s_b[k][t], t<64
    for (int i = tid; i < 1024; i += 256) {
        int t = i >> 4, k = i & 15;
        float2 cs = g_tab[i];
        s_bc[k * 65 + t] = cs.x;
        s_bs[k * 65 + t] = cs.y;
    }
    __syncthreads();

    int qs = tid & 63, pg = tid >> 6;               // 4 p-groups of 16 rows
    float* ob = out + (size_t)img * 65536 + (size_t)tile * 64 * 256;

    if (qs != 0) {
        float c[16], s[16];
#pragma unroll
        for (int w = 0; w < 16; w++) {
            c[w] = s_bc[w * 65 + qs];               // conflict-free LDS
            s[w] = s_bs[w * 65 + qs];
        }
        for (int pi = 0; pi < 16; pi++) {
            int p = pg * 16 + pi;
            const float4* z4 = (const float4*)(s_z + p * ZS);  // broadcast LDS.128
            float z[32];
#pragma unroll
            for (int t = 0; t < 8; t++) {
                float4 v = z4[t];
                z[4 * t] = v.x; z[4 * t + 1] = v.y; z[4 * t + 2] = v.z; z[4 * t + 3] = v.w;
            }
            float Ce = 0.f, Co = 0.f, Se = 0.f, So = 0.f;
#pragma unroll
            for (int m = 0; m < 8; m++) {
                Ce = fmaf(z[2 * m],          c[2 * m],     Ce);
                Co = fmaf(z[2 * m + 1],      c[2 * m + 1], Co);
                Se = fmaf(z[16 + 2 * m],     s[2 * m],     Se);
                So = fmaf(z[16 + 2 * m + 1], s[2 * m + 1], So);
            }
            float t1 = Ce + Co, t2 = Se + So;
            float t3 = Ce - Co, t4 = So - Se;
            float* op = ob + (size_t)p * 256;
            op[qs]        = t1 + t2;
            op[256 - qs]  = t1 - t2;
            op[128 - qs]  = t3 + t4;
            op[128 + qs]  = t3 - t4;
        }
    }

    // specials: q in {0,64,128,192}; warps 0-1 uniform, one row per thread
    if (tid < 64) {
        int p = tid;
        const float4* z4 = (const float4*)(s_z + p * ZS);
        float z[32];
#pragma unroll
        for (int t = 0; t < 8; t++) {
            float4 v = z4[t];
            z[4 * t] = v.x; z[4 * t + 1] = v.y; z[4 * t + 2] = v.z; z[4 * t + 3] = v.w;
        }
        float o0 = 0.f, o128 = 0.f, c64 = 0.f, s64 = 0.f;
#pragma unroll
        for (int w = 0; w < 16; w++) {
            o0 += z[w];
            o128 += (w & 1) ? -z[w] : z[w];
        }
#pragma unroll
        for (int m = 0; m < 4; m++) {
            c64 += z[4 * m]          - z[4 * m + 2];
            s64 += z[16 + 4 * m + 1] - z[16 + 4 * m + 3];
        }
        float* op = ob + (size_t)p * 256;
        op[0]   = o0;
        op[128] = o128;
        op[64]  = c64 + s64;
        op[192] = c64 - s64;
    }
}

extern "C" void kernel_launch(void* const* d_in, const int* in_sizes, int n_in,
                              void* d_out, int out_size) {
    const float* x   = (const float*)d_in[0];
    const float* wre = (const float*)d_in[1];
    const float* wim = (const float*)d_in[2];
    float* out = (float*)d_out;

    cudaFuncSetAttribute(k1, cudaFuncAttributeMaxDynamicSharedMemorySize, 73728);

    k_init<<<16, 256>>>();
    k1 <<<NIMG, 256, 73728>>>(x);
    k2 <<<NIMG, 256>>>(wre, wim);
    k3 <<<NIMG * 4, 256>>>(out);
}

// round 14
// speedup vs baseline: 1.5031x; 1.1078x over previous
#include <cuda_runtime.h>
#include <math.h>

// SpectralConv2d: B=8, C=64, H=W=256, modes 16x16.
// Folded partial-DFT stages. R13: k1 split into k1a (H-DFT, low-smem, high
// occupancy, writes A to global) + k1b (tiny corner W-DFT). k2/k3 = R11.

#define NIMG 512              // B*C images of 256x256

// tables (angle a = 2*pi/256)
__device__ float2 g_tab[256 * 16];   // [t][k] (cos akt, sin akt)
__device__ float  g_tabC[16 * 256];  // [k][t] cos
__device__ float  g_tabS[16 * 256];  // [k][t] sin
// k1 phase-1 folded table: [h][32] for h=0..63
__device__ float  g_tab1[64 * 32];
// A[img][k][x] intermediate (H-DFT result), 16MB
__device__ float2 g_A[(size_t)NIMG * 16 * 256];
// X_ft corner per (b,i): [img][k*16+w], complex
__device__ float2 g_X[NIMG * 256];
// Z per (b,o): [img][p][j], j<16: cos-coeff, j>=16: sin-coeff
__device__ float  g_Z[(size_t)NIMG * 256 * 32];

// ---------------- table init ------------------------------------------------
__global__ void k_init() {
    int i = blockIdx.x * blockDim.x + threadIdx.x;
    if (i < 4096) {
        int t = i >> 4, k = i & 15;
        int m = (t * k) & 255;
        double s, c;
        sincospi((double)m / 128.0, &s, &c);       // angle = 2*pi*m/256
        g_tab[i] = make_float2((float)c, (float)s);
        g_tabC[k * 256 + t] = (float)c;
        g_tabS[k * 256 + t] = (float)s;
    }
    if (i < 2048) {
        int h = i >> 5, j = i & 31;
        int m = j & 7;
        int k = ((j & 15) < 8) ? (2 * m) : (2 * m + 1);
        int mm = (h * k) & 255;
        double s, c;
        sincospi((double)mm / 128.0, &s, &c);
        g_tab1[i] = (j < 16) ? (float)c : (float)s;
    }
}

// ---------------- K1a: folded partial DFT over H -> g_A ---------------------
// Block = image, thread = x column. 8KB smem only -> 4 blocks/SM.
__global__ void __launch_bounds__(256, 4) k1a(const float* __restrict__ x) {
    __shared__ __align__(16) float s_t1[64 * 32];   // 8KB
    int img = blockIdx.x, tid = threadIdx.x;

    for (int i = tid; i < 2048; i += 256) s_t1[i] = g_tab1[i];
    __syncthreads();

    const float* xp = x + (size_t)img * 65536 + tid;
    float x0   = xp[0];
    float x64v = xp[64 * 256];
    float x128 = xp[128 * 256];
    float x192 = xp[192 * 256];

    float arE[8], arO[8], asE[8], asO[8];
#pragma unroll
    for (int m = 0; m < 8; m++) { arE[m] = 0.f; arO[m] = 0.f; asE[m] = 0.f; asO[m] = 0.f; }

#pragma unroll 2
    for (int h = 1; h < 64; h++) {
        float a1 = xp[(size_t)h * 256];
        float a2 = xp[(size_t)(256 - h) * 256];
        float a3 = xp[(size_t)(128 - h) * 256];
        float a4 = xp[(size_t)(128 + h) * 256];
        float u1 = a1 + a2, v1 = a1 - a2;
        float u2 = a3 + a4, v2 = a3 - a4;
        float uE = u1 + u2, uO = u1 - u2;
        float vE = v1 - v2, vO = v1 + v2;
        const float4* t4 = (const float4*)(s_t1 + h * 32);   // broadcast LDS.128
        float4 cE0 = t4[0], cE1 = t4[1], cO0 = t4[2], cO1 = t4[3];
        float4 sE0 = t4[4], sE1 = t4[5], sO0 = t4[6], sO1 = t4[7];
        arE[0] = fmaf(uE, cE0.x, arE[0]); arE[1] = fmaf(uE, cE0.y, arE[1]);
        arE[2] = fmaf(uE, cE0.z, arE[2]); arE[3] = fmaf(uE, cE0.w, arE[3]);
        arE[4] = fmaf(uE, cE1.x, arE[4]); arE[5] = fmaf(uE, cE1.y, arE[5]);
        arE[6] = fmaf(uE, cE1.z, arE[6]); arE[7] = fmaf(uE, cE1.w, arE[7]);
        arO[0] = fmaf(uO, cO0.x, arO[0]); arO[1] = fmaf(uO, cO0.y, arO[1]);
        arO[2] = fmaf(uO, cO0.z, arO[2]); arO[3] = fmaf(uO, cO0.w, arO[3]);
        arO[4] = fmaf(uO, cO1.x, arO[4]); arO[5] = fmaf(uO, cO1.y, arO[5]);
        arO[6] = fmaf(uO, cO1.z, arO[6]); arO[7] = fmaf(uO, cO1.w, arO[7]);
        asE[0] = fmaf(vE, sE0.x, asE[0]); asE[1] = fmaf(vE, sE0.y, asE[1]);
        asE[2] = fmaf(vE, sE0.z, asE[2]); asE[3] = fmaf(vE, sE0.w, asE[3]);
        asE[4] = fmaf(vE, sE1.x, asE[4]); asE[5] = fmaf(vE, sE1.y, asE[5]);
        asE[6] = fmaf(vE, sE1.z, asE[6]); asE[7] = fmaf(vE, sE1.w, asE[7]);
        asO[0] = fmaf(vO, sO0.x, asO[0]); asO[1] = fmaf(vO, sO0.y, asO[1]);
        asO[2] = fmaf(vO, sO0.z, asO[2]); asO[3] = fmaf(vO, sO0.w, asO[3]);
        asO[4] = fmaf(vO, sO1.x, asO[4]); asO[5] = fmaf(vO, sO1.y, asO[5]);
        asO[6] = fmaf(vO, sO1.z, asO[6]); asO[7] = fmaf(vO, sO1.w, asO[7]);
    }

    float u64v = x64v + x192, v64v = x64v - x192;
    float2* ap = g_A + (size_t)img * 4096 + tid;
    float sgn = 1.f;
#pragma unroll
    for (int m = 0; m < 8; m++) {
        ap[(2 * m) * 256]     = make_float2(x0 + x128 + arE[m] + sgn * u64v, asE[m]);
        ap[(2 * m + 1) * 256] = make_float2(x0 - x128 + arO[m], asO[m] + sgn * v64v);
        sgn = -sgn;
    }
}

// ---------------- K1b: corner DFT over W: A -> X ----------------------------
// Block = image; tid = k*16+w.
__global__ void __launch_bounds__(256) k1b() {
    extern __shared__ __align__(16) char smem_raw[];
    float2* s_A   = (float2*)smem_raw;             // [k][x] 32KB
    float2* s_tab = (float2*)(smem_raw + 32768);   // [t][16] 32KB
    int img = blockIdx.x, tid = threadIdx.x;

    {
        const float4* asrc = (const float4*)(g_A + (size_t)img * 4096);
        float4* adst = (float4*)s_A;
        adst[tid]        = asrc[tid];
        adst[tid + 256]  = asrc[tid + 256];
        adst[tid + 512]  = asrc[tid + 512];
        adst[tid + 768]  = asrc[tid + 768];
        adst[tid + 1024] = asrc[tid + 1024];
        adst[tid + 1280] = asrc[tid + 1280];
        adst[tid + 1536] = asrc[tid + 1536];
        adst[tid + 1792] = asrc[tid + 1792];
    }
    for (int i = tid; i < 4096; i += 256) s_tab[i] = g_tab[i];
    __syncthreads();

    int k = tid >> 4, w = tid & 15;
    float xr = 0.f, xi = 0.f;
#pragma unroll 4
    for (int xx = 0; xx < 256; xx++) {
        float2 a  = s_A[k * 256 + xx];     // broadcast
        float2 cs = s_tab[xx * 16 + w];
        xr += a.x * cs.x - a.y * cs.y;
        xi -= a.y * cs.x + a.x * cs.y;
    }
    g_X[img * 256 + tid] = make_float2(xr, xi);
}

// ---------------- K2 (fused): channel mix + inverse-k DFT -> Z --------------
__global__ void __launch_bounds__(256) k2(const float* __restrict__ wre,
                                          const float* __restrict__ wim) {
    __shared__ float2 sG[256];
    int b = blockIdx.x >> 6, o = blockIdx.x & 63, tid = threadIdx.x;

    {
        const float2* Xb = g_X + b * 64 * 256;
        float gr = 0.f, gi = 0.f;
#pragma unroll 4
        for (int i = 0; i < 64; i++) {
            float2 xv = Xb[i * 256 + tid];
            float wr = wre[(size_t)(i * 64 + o) * 256 + tid];
            float wi = wim[(size_t)(i * 64 + o) * 256 + tid];
            gr = fmaf(xv.x, wr, fmaf(-xv.y, wi, gr));
            gi = fmaf(xv.x, wi, fmaf( xv.y, wr, gi));
        }
        sG[tid] = make_float2(gr, gi);
    }
    __syncthreads();

    int p = tid;
    float2 tp[16];
#pragma unroll
    for (int k = 0; k < 16; k++)
        tp[k] = make_float2(g_tabC[k * 256 + p], g_tabS[k * 256 + p]);

    float zc[16], zs[16];
#pragma unroll
    for (int w = 0; w < 16; w++) {
        float yr = 0.f, yi = 0.f;
#pragma unroll
        for (int k = 0; k < 16; k++) {
            float2 g = sG[k * 16 + w];
            yr += g.x * tp[k].x - g.y * tp[k].y;
            yi += g.x * tp[k].y + g.y * tp[k].x;
        }
        zc[w] = yr; zs[w] = -yi;
    }
    const float s1 = 1.0f / 65536.0f, s2 = 2.0f / 65536.0f;
    zc[0] *= s1; zs[0] = 0.f;
#pragma unroll
    for (int w = 1; w < 16; w++) { zc[w] *= s2; zs[w] *= s2; }

    float4* z4 = (float4*)(g_Z + ((size_t)blockIdx.x * 256 + p) * 32);
    z4[0] = make_float4(zc[0],  zc[1],  zc[2],  zc[3]);
    z4[1] = make_float4(zc[4],  zc[5],  zc[6],  zc[7]);
    z4[2] = make_float4(zc[8],  zc[9],  zc[10], zc[11]);
    z4[3] = make_float4(zc[12], zc[13], zc[14], zc[15]);
    z4[4] = make_float4(zs[0],  zs[1],  zs[2],  zs[3]);
    z4[5] = make_float4(zs[4],  zs[5],  zs[6],  zs[7]);
    z4[6] = make_float4(zs[8],  zs[9],  zs[10], zs[11]);
    z4[7] = make_float4(zs[12], zs[13], zs[14], zs[15]);
}

// ---------------- K3: folded inverse W transform (R11 version) --------------
#define ZS 36
__global__ void __launch_bounds__(256) k3(float* __restrict__ out) {
    __shared__ __align__(16) float s_z[64 * ZS];     // 9KB z tile (padded)
    __shared__ float s_bc[16 * 65];                  // basis cos [w][qs]
    __shared__ float s_bs[16 * 65];                  // basis sin [w][qs]
    int img = blockIdx.x >> 2, tile = blockIdx.x & 3, tid = threadIdx.x;

    {
        const float4* zsrc = (const float4*)(g_Z + (size_t)img * 8192 + tile * 2048);
        float4* zdst = (float4*)s_z;
#pragma unroll
        for (int it = 0; it < 2; it++) {
            int i = tid + it * 256;
            int row = i >> 3, t = i & 7;
            zdst[row * (ZS / 4) + t] = zsrc[i];
        }
    }
    for (int i = tid; i < 1024; i += 256) {
        int t = i >> 4, k = i & 15;
        float2 cs = g_tab[i];
        s_bc[k * 65 + t] = cs.x;
        s_bs[k * 65 + t] = cs.y;
    }
    __syncthreads();

    int qs = tid & 63, pg = tid >> 6;
    float* ob = out + (size_t)img * 65536 + (size_t)tile * 64 * 256;

    if (qs != 0) {
        float c[16], s[16];
#pragma unroll
        for (int w = 0; w < 16; w++) {
            c[w] = s_bc[w * 65 + qs];
            s[w] = s_bs[w * 65 + qs];
        }
        for (int pi = 0; pi < 16; pi++) {
            int p = pg * 16 + pi;
            const float4* z4 = (const float4*)(s_z + p * ZS);
            float z[32];
#pragma unroll
            for (int t = 0; t < 8; t++) {
                float4 v = z4[t];
                z[4 * t] = v.x; z[4 * t + 1] = v.y; z[4 * t + 2] = v.z; z[4 * t + 3] = v.w;
            }
            float Ce = 0.f, Co = 0.f, Se = 0.f, So = 0.f;
#pragma unroll
            for (int m = 0; m < 8; m++) {
                Ce = fmaf(z[2 * m],          c[2 * m],     Ce);
                Co = fmaf(z[2 * m + 1],      c[2 * m + 1], Co);
                Se = fmaf(z[16 + 2 * m],     s[2 * m],     Se);
                So = fmaf(z[16 + 2 * m + 1], s[2 * m + 1], So);
            }
            float t1 = Ce + Co, t2 = Se + So;
            float t3 = Ce - Co, t4 = So - Se;
            float* op = ob + (size_t)p * 256;
            op[qs]        = t1 + t2;
            op[256 - qs]  = t1 - t2;
            op[128 - qs]  = t3 + t4;
            op[128 + qs]  = t3 - t4;
        }
    }

    if (tid < 64) {
        int p = tid;
        const float4* z4 = (const float4*)(s_z + p * ZS);
        float z[32];
#pragma unroll
        for (int t = 0; t < 8; t++) {
            float4 v = z4[t];
            z[4 * t] = v.x; z[4 * t + 1] = v.y; z[4 * t + 2] = v.z; z[4 * t + 3] = v.w;
        }
        float o0 = 0.f, o128 = 0.f, c64 = 0.f, s64 = 0.f;
#pragma unroll
        for (int w = 0; w < 16; w++) {
            o0 += z[w];
            o128 += (w & 1) ? -z[w] : z[w];
        }
#pragma unroll
        for (int m = 0; m < 4; m++) {
            c64 += z[4 * m]          - z[4 * m + 2];
            s64 += z[16 + 4 * m + 1] - z[16 + 4 * m + 3];
        }
        float* op = ob + (size_t)p * 256;
        op[0]   = o0;
        op[128] = o128;
        op[64]  = c64 + s64;
        op[192] = c64 - s64;
    }
}

extern "C" void kernel_launch(void* const* d_in, const int* in_sizes, int n_in,
                              void* d_out, int out_size) {
    const float* x   = (const float*)d_in[0];
    const float* wre = (const float*)d_in[1];
    const float* wim = (const float*)d_in[2];
    float* out = (float*)d_out;

    cudaFuncSetAttribute(k1b, cudaFuncAttributeMaxDynamicSharedMemorySize, 65536);

    k_init<<<16, 256>>>();
    k1a<<<NIMG, 256>>>(x);
    k1b<<<NIMG, 256, 65536>>>();
    k2 <<<NIMG, 256>>>(wre, wim);
    k3 <<<NIMG * 4, 256>>>(out);
}